// round 3
// baseline (speedup 1.0000x reference)
#include <cuda_runtime.h>
#include <math.h>

// Problem constants
#define LN   6
#define HN   12
#define DN   64
#define CN   768
#define VN   32000
#define BN_  2
#define TN   1024
#define BT   2048          // B*T
#define FN   3072          // 4*C
#define QKVN 2304          // 3*C

// ---------------- scratch (device globals; no allocations allowed) ----------
__device__ float g_h   [BT * CN];                       // residual stream
__device__ float g_ain [BT * CN];                       // layernorm output
__device__ float g_qkv [BT * QKVN];                     // fused q|k|v
__device__ float g_w   [(size_t)BN_ * HN * TN * TN];    // attn scores / probs (100MB)
__device__ float g_att [BT * CN];                       // attention output (B,T,H*D)
__device__ float g_ffn [BT * FN];                       // MLP hidden
__device__ float g_wt  [CN * QKVN];                     // transposed qkv weights (C x 3C)

// ---------------- embedding -------------------------------------------------
__global__ void embed_kernel(const int* __restrict__ x, const float* __restrict__ tok,
                             const float* __restrict__ pos, float* __restrict__ out) {
    int idx = blockIdx.x * 256 + threadIdx.x;
    if (idx >= BT * CN) return;
    int bt = idx / CN, c = idx % CN;
    int t = bt % TN;
    out[idx] = tok[(size_t)x[bt] * CN + c] + pos[t * CN + c];
}

// ---------------- weight transpose: (H,C,D)x3 -> (C, 3*H*D) -----------------
__global__ void transpose_qkv_kernel(const float* __restrict__ Wq, const float* __restrict__ Wk,
                                     const float* __restrict__ Wv, float* __restrict__ out) {
    int idx = blockIdx.x * 256 + threadIdx.x;
    const int per = HN * CN * DN;
    if (idx >= 3 * per) return;
    int which = idx / per, r = idx % per;
    int h = r / (CN * DN);
    int c = (r / DN) % CN;
    int d = r % DN;
    const float* W = (which == 0) ? Wq : (which == 1) ? Wk : Wv;
    out[c * QKVN + which * CN + h * DN + d] = W[(size_t)(h * CN + c) * DN + d];
}

// ---------------- layernorm (one block of 256 per row, C=768) ---------------
__global__ void layernorm_kernel(const float* __restrict__ x, const float* __restrict__ g,
                                 const float* __restrict__ b, float* __restrict__ out) {
    int row = blockIdx.x;
    const float* xr = x + (size_t)row * CN;
    float* orow = out + (size_t)row * CN;
    int tid = threadIdx.x;
    __shared__ float sred[32];

    float s = 0.f;
    for (int c = tid; c < CN; c += 256) s += xr[c];
    #pragma unroll
    for (int o = 16; o; o >>= 1) s += __shfl_xor_sync(0xffffffffu, s, o);
    if ((tid & 31) == 0) sred[tid >> 5] = s;
    __syncthreads();
    if (tid < 32) {
        float v = (tid < 8) ? sred[tid] : 0.f;
        #pragma unroll
        for (int o = 4; o; o >>= 1) v += __shfl_xor_sync(0xffffffffu, v, o);
        if (tid == 0) sred[0] = v;
    }
    __syncthreads();
    float mean = sred[0] * (1.0f / CN);
    __syncthreads();

    float vs = 0.f;
    for (int c = tid; c < CN; c += 256) { float d = xr[c] - mean; vs += d * d; }
    #pragma unroll
    for (int o = 16; o; o >>= 1) vs += __shfl_xor_sync(0xffffffffu, vs, o);
    if ((tid & 31) == 0) sred[tid >> 5] = vs;
    __syncthreads();
    if (tid < 32) {
        float v = (tid < 8) ? sred[tid] : 0.f;
        #pragma unroll
        for (int o = 4; o; o >>= 1) v += __shfl_xor_sync(0xffffffffu, v, o);
        if (tid == 0) sred[0] = v;
    }
    __syncthreads();
    float inv = rsqrtf(sred[0] * (1.0f / CN) + 1e-5f);
    for (int c = tid; c < CN; c += 256)
        orow[c] = (xr[c] - mean) * inv * g[c] + b[c];
}

// ---------------- generic fp32 SGEMM: C = A(MxK) @ B(KxN) [+bias][relu][+res]
// Requires M%128==0, N%128==0, K%8==0 (always true here).
__global__ void sgemm_kernel(const float* __restrict__ A, const float* __restrict__ Bm,
                             float* __restrict__ Cm, const float* __restrict__ bias,
                             const float* __restrict__ res,
                             int M, int N, int K, int relu) {
    __shared__ float As[8][128];
    __shared__ float Bs[8][128];
    int tid = threadIdx.x;
    int arow = tid >> 1, acol = (tid & 1) * 4;     // A tile 128x8, one float4 each
    int brow = tid >> 5, bcol = (tid & 31) * 4;    // B tile 8x128, one float4 each
    int trow = (tid >> 4) * 8, tcol = (tid & 15) * 8;

    const float* Ap = A + (size_t)(blockIdx.y * 128) * K;
    const float* Bp = Bm + blockIdx.x * 128;

    float acc[8][8];
    #pragma unroll
    for (int i = 0; i < 8; i++)
        #pragma unroll
        for (int j = 0; j < 8; j++) acc[i][j] = 0.f;

    for (int k0 = 0; k0 < K; k0 += 8) {
        float4 av = *(const float4*)(Ap + (size_t)arow * K + k0 + acol);
        As[acol + 0][arow] = av.x;
        As[acol + 1][arow] = av.y;
        As[acol + 2][arow] = av.z;
        As[acol + 3][arow] = av.w;
        float4 bv = *(const float4*)(Bp + (size_t)(k0 + brow) * N + bcol);
        *(float4*)(&Bs[brow][bcol]) = bv;
        __syncthreads();
        #pragma unroll
        for (int kk = 0; kk < 8; kk++) {
            float ar[8], br[8];
            #pragma unroll
            for (int i = 0; i < 8; i++) ar[i] = As[kk][trow + i];
            #pragma unroll
            for (int j = 0; j < 8; j++) br[j] = Bs[kk][tcol + j];
            #pragma unroll
            for (int i = 0; i < 8; i++)
                #pragma unroll
                for (int j = 0; j < 8; j++) acc[i][j] = fmaf(ar[i], br[j], acc[i][j]);
        }
        __syncthreads();
    }

    int gm = blockIdx.y * 128 + trow, gn = blockIdx.x * 128 + tcol;
    #pragma unroll
    for (int i = 0; i < 8; i++) {
        size_t ro = (size_t)(gm + i) * N + gn;
        #pragma unroll
        for (int j = 0; j < 8; j++) {
            float v = acc[i][j];
            if (bias) v += bias[gn + j];
            if (relu) v = fmaxf(v, 0.f);
            if (res)  v += res[ro + j];
            Cm[ro + j] = v;
        }
    }
}

// ---------------- attention scores: S[b,h,t,s] = q.k (raw, causal tiles only)
__global__ void scores_kernel(const float* __restrict__ qkv, float* __restrict__ w) {
    int st = blockIdx.x, tt = blockIdx.y, z = blockIdx.z;
    if (st > tt) return;                           // fully-masked tile
    int b = z / HN, h = z % HN;
    int t0 = tt * 64, s0 = st * 64;
    __shared__ float qs[64][65], ks[64][65];
    int tid = threadIdx.x;
    #pragma unroll
    for (int i = 0; i < 16; i++) {
        int idx = tid + i * 256;
        int r = idx >> 6, d = idx & 63;
        qs[r][d] = qkv[((size_t)(b * TN + t0 + r)) * QKVN + h * DN + d];
        ks[r][d] = qkv[((size_t)(b * TN + s0 + r)) * QKVN + CN + h * DN + d];
    }
    __syncthreads();
    int trow = (tid >> 4) << 2, tcol = (tid & 15) << 2;
    float acc[4][4] = {};
    #pragma unroll
    for (int d = 0; d < 64; d++) {
        float a[4], bb[4];
        #pragma unroll
        for (int i = 0; i < 4; i++) a[i] = qs[trow + i][d];
        #pragma unroll
        for (int j = 0; j < 4; j++) bb[j] = ks[tcol + j][d];
        #pragma unroll
        for (int i = 0; i < 4; i++)
            #pragma unroll
            for (int j = 0; j < 4; j++) acc[i][j] = fmaf(a[i], bb[j], acc[i][j]);
    }
    size_t base = (size_t)z * TN * TN;
    #pragma unroll
    for (int i = 0; i < 4; i++)
        #pragma unroll
        for (int j = 0; j < 4; j++)
            w[base + (size_t)(t0 + trow + i) * TN + s0 + tcol + j] = acc[i][j];
}

// ---------------- causal softmax in-place over rows of g_w ------------------
__global__ void softmax_kernel(float* __restrict__ w) {
    int row = blockIdx.x;            // 0 .. B*H*T-1
    int t = row % TN;
    float* wr = w + (size_t)row * TN;
    int n = t + 1;
    int tid = threadIdx.x;           // 128 threads
    const float scale = rsqrtf((float)CN);
    __shared__ float sred[32];

    float mx = -1e30f;
    for (int s = tid; s < n; s += 128) mx = fmaxf(mx, wr[s]);
    #pragma unroll
    for (int o = 16; o; o >>= 1) mx = fmaxf(mx, __shfl_xor_sync(0xffffffffu, mx, o));
    if ((tid & 31) == 0) sred[tid >> 5] = mx;
    __syncthreads();
    if (tid < 32) {
        float v = (tid < 4) ? sred[tid] : -1e30f;
        #pragma unroll
        for (int o = 2; o; o >>= 1) v = fmaxf(v, __shfl_xor_sync(0xffffffffu, v, o));
        if (tid == 0) sred[0] = v;
    }
    __syncthreads();
    float m = sred[0];
    __syncthreads();

    float sum = 0.f;
    for (int s = tid; s < n; s += 128) {
        float e = __expf(scale * (wr[s] - m));
        wr[s] = e;
        sum += e;
    }
    #pragma unroll
    for (int o = 16; o; o >>= 1) sum += __shfl_xor_sync(0xffffffffu, sum, o);
    if ((tid & 31) == 0) sred[tid >> 5] = sum;
    __syncthreads();
    if (tid < 32) {
        float v = (tid < 4) ? sred[tid] : 0.f;
        #pragma unroll
        for (int o = 2; o; o >>= 1) v += __shfl_xor_sync(0xffffffffu, v, o);
        if (tid == 0) sred[0] = v;
    }
    __syncthreads();
    float inv = 1.f / sred[0];
    for (int s = tid; s < n; s += 128) wr[s] *= inv;
    for (int s = n + tid; s < TN; s += 128) wr[s] = 0.f;
}

// ---------------- O = P @ V, writes (B,T,H*D) layout -------------------------
__global__ void wv_kernel(const float* __restrict__ qkv, const float* __restrict__ w,
                          float* __restrict__ att) {
    int tt = blockIdx.x, z = blockIdx.z;
    int b = z / HN, h = z % HN;
    int t0 = tt * 64;
    __shared__ float ws[64][65], vs[64][65];
    int tid = threadIdx.x;
    int trow = (tid >> 4) << 2, tcol = (tid & 15) << 2;
    float acc[4][4] = {};
    for (int st = 0; st <= tt; st++) {     // causal: only s-tiles <= t-tile
        int s0 = st * 64;
        #pragma unroll
        for (int i = 0; i < 16; i++) {
            int idx = tid + i * 256;
            int r = idx >> 6, cc = idx & 63;
            ws[r][cc] = w[((size_t)z * TN + t0 + r) * TN + s0 + cc];
            vs[r][cc] = qkv[((size_t)(b * TN + s0 + r)) * QKVN + 2 * CN + h * DN + cc];
        }
        __syncthreads();
        #pragma unroll
        for (int ss = 0; ss < 64; ss++) {
            float a[4], bb[4];
            #pragma unroll
            for (int i = 0; i < 4; i++) a[i] = ws[trow + i][ss];
            #pragma unroll
            for (int j = 0; j < 4; j++) bb[j] = vs[ss][tcol + j];
            #pragma unroll
            for (int i = 0; i < 4; i++)
                #pragma unroll
                for (int j = 0; j < 4; j++) acc[i][j] = fmaf(a[i], bb[j], acc[i][j]);
        }
        __syncthreads();
    }
    #pragma unroll
    for (int i = 0; i < 4; i++)
        #pragma unroll
        for (int j = 0; j < 4; j++)
            att[((size_t)(b * TN + t0 + trow + i)) * CN + h * DN + tcol + j] = acc[i][j];
}

// ---------------- host orchestration ----------------------------------------
extern "C" void kernel_launch(void* const* d_in, const int* in_sizes, int n_in,
                              void* d_out, int out_size) {
    const int*   x       = (const int*)  d_in[0];
    const float* tok_emb = (const float*)d_in[1];
    const float* pos_emb = (const float*)d_in[2];
    const float* Wq      = (const float*)d_in[3];
    const float* Wk      = (const float*)d_in[4];
    const float* Wv      = (const float*)d_in[5];
    const float* Wo      = (const float*)d_in[6];
    const float* bo      = (const float*)d_in[7];
    const float* ln1_g   = (const float*)d_in[8];
    const float* ln1_b   = (const float*)d_in[9];
    const float* ln2_g   = (const float*)d_in[10];
    const float* ln2_b   = (const float*)d_in[11];
    const float* W1      = (const float*)d_in[12];
    const float* b1      = (const float*)d_in[13];
    const float* W2      = (const float*)d_in[14];
    const float* b2      = (const float*)d_in[15];
    const float* lnf_g   = (const float*)d_in[16];
    const float* lnf_b   = (const float*)d_in[17];
    const float* Wh      = (const float*)d_in[18];
    const float* bh      = (const float*)d_in[19];
    float* out = (float*)d_out;

    float *ph, *pain, *pqkv, *pw, *patt, *pffn, *pwt;
    cudaGetSymbolAddress((void**)&ph,   g_h);
    cudaGetSymbolAddress((void**)&pain, g_ain);
    cudaGetSymbolAddress((void**)&pqkv, g_qkv);
    cudaGetSymbolAddress((void**)&pw,   g_w);
    cudaGetSymbolAddress((void**)&patt, g_att);
    cudaGetSymbolAddress((void**)&pffn, g_ffn);
    cudaGetSymbolAddress((void**)&pwt,  g_wt);

    const int HCD = HN * CN * DN;

    embed_kernel<<<(BT * CN + 255) / 256, 256>>>(x, tok_emb, pos_emb, ph);

    for (int l = 0; l < LN; l++) {
        layernorm_kernel<<<BT, 256>>>(ph, ln1_g + l * CN, ln1_b + l * CN, pain);
        transpose_qkv_kernel<<<(3 * HCD + 255) / 256, 256>>>(
            Wq + (size_t)l * HCD, Wk + (size_t)l * HCD, Wv + (size_t)l * HCD, pwt);
        sgemm_kernel<<<dim3(QKVN / 128, BT / 128), 256>>>(
            pain, pwt, pqkv, nullptr, nullptr, BT, QKVN, CN, 0);
        scores_kernel<<<dim3(TN / 64, TN / 64, BN_ * HN), 256>>>(pqkv, pw);
        softmax_kernel<<<BN_ * HN * TN, 128>>>(pw);
        wv_kernel<<<dim3(TN / 64, 1, BN_ * HN), 256>>>(pqkv, pw, patt);
        sgemm_kernel<<<dim3(CN / 128, BT / 128), 256>>>(
            patt, Wo + (size_t)l * CN * CN, ph, bo + l * CN, ph, BT, CN, CN, 0);
        layernorm_kernel<<<BT, 256>>>(ph, ln2_g + l * CN, ln2_b + l * CN, pain);
        sgemm_kernel<<<dim3(FN / 128, BT / 128), 256>>>(
            pain, W1 + (size_t)l * CN * FN, pffn, b1 + l * FN, nullptr, BT, FN, CN, 1);
        sgemm_kernel<<<dim3(CN / 128, BT / 128), 256>>>(
            pffn, W2 + (size_t)l * FN * CN, ph, b2 + l * CN, ph, BT, CN, FN, 0);
    }

    layernorm_kernel<<<BT, 256>>>(ph, lnf_g, lnf_b, pain);
    sgemm_kernel<<<dim3(VN / 128, BT / 128), 256>>>(
        pain, Wh, out, bh, nullptr, BT, VN, CN, 0);
}

// round 6
// speedup vs baseline: 2.0451x; 2.0451x over previous
#include <cuda_runtime.h>
#include <math.h>

// Problem constants
#define LN   6
#define HN   12
#define DN   64
#define CN   768
#define VN   32000
#define BN_  2
#define TN   1024
#define BT   2048          // B*T
#define FN   3072          // 4*C
#define QKVN 2304          // 3*C

// ---------------- scratch (device globals; no allocations allowed) ----------
__device__ float g_h   [BT * CN];                       // residual stream
__device__ float g_ain [BT * CN];                       // layernorm output
__device__ float g_qkv [BT * QKVN];                     // fused q|k|v
__device__ float g_w   [(size_t)BN_ * HN * TN * TN];    // attn scores / probs (100MB)
__device__ float g_att [BT * CN];                       // attention output (B,T,H*D)
__device__ float g_ffn [BT * FN];                       // MLP hidden
__device__ float g_wt  [CN * QKVN];                     // transposed qkv weights (C x 3C)

// ---------------- embedding -------------------------------------------------
__global__ void embed_kernel(const int* __restrict__ x, const float* __restrict__ tok,
                             const float* __restrict__ pos, float* __restrict__ out) {
    int idx = blockIdx.x * 256 + threadIdx.x;
    if (idx >= BT * CN) return;
    int bt = idx / CN, c = idx % CN;
    int t = bt % TN;
    out[idx] = tok[(size_t)x[bt] * CN + c] + pos[t * CN + c];
}

// ---------------- weight transpose: (H,C,D)x3 -> (C, 3*H*D) -----------------
__global__ void transpose_qkv_kernel(const float* __restrict__ Wq, const float* __restrict__ Wk,
                                     const float* __restrict__ Wv, float* __restrict__ out) {
    int idx = blockIdx.x * 256 + threadIdx.x;
    const int per = HN * CN * DN;
    if (idx >= 3 * per) return;
    int which = idx / per, r = idx % per;
    int h = r / (CN * DN);
    int c = (r / DN) % CN;
    int d = r % DN;
    const float* W = (which == 0) ? Wq : (which == 1) ? Wk : Wv;
    out[c * QKVN + which * CN + h * DN + d] = W[(size_t)(h * CN + c) * DN + d];
}

// ---------------- layernorm (one block of 256 per row, C=768) ---------------
__global__ void layernorm_kernel(const float* __restrict__ x, const float* __restrict__ g,
                                 const float* __restrict__ b, float* __restrict__ out) {
    int row = blockIdx.x;
    const float* xr = x + (size_t)row * CN;
    float* orow = out + (size_t)row * CN;
    int tid = threadIdx.x;
    __shared__ float sred[32];

    float s = 0.f;
    for (int c = tid; c < CN; c += 256) s += xr[c];
    #pragma unroll
    for (int o = 16; o; o >>= 1) s += __shfl_xor_sync(0xffffffffu, s, o);
    if ((tid & 31) == 0) sred[tid >> 5] = s;
    __syncthreads();
    if (tid < 32) {
        float v = (tid < 8) ? sred[tid] : 0.f;
        #pragma unroll
        for (int o = 4; o; o >>= 1) v += __shfl_xor_sync(0xffffffffu, v, o);
        if (tid == 0) sred[0] = v;
    }
    __syncthreads();
    float mean = sred[0] * (1.0f / CN);
    __syncthreads();

    float vs = 0.f;
    for (int c = tid; c < CN; c += 256) { float d = xr[c] - mean; vs += d * d; }
    #pragma unroll
    for (int o = 16; o; o >>= 1) vs += __shfl_xor_sync(0xffffffffu, vs, o);
    if ((tid & 31) == 0) sred[tid >> 5] = vs;
    __syncthreads();
    if (tid < 32) {
        float v = (tid < 8) ? sred[tid] : 0.f;
        #pragma unroll
        for (int o = 4; o; o >>= 1) v += __shfl_xor_sync(0xffffffffu, v, o);
        if (tid == 0) sred[0] = v;
    }
    __syncthreads();
    float inv = rsqrtf(sred[0] * (1.0f / CN) + 1e-5f);
    for (int c = tid; c < CN; c += 256)
        orow[c] = (xr[c] - mean) * inv * g[c] + b[c];
}

// ---------------- TF32 tensor-core GEMM -------------------------------------
// C = A(MxK) @ B(KxN) [+bias][relu][+res]; M%128==0, N%128==0, K%32==0.
// CTA tile 128x128x32; 8 warps, each 64x32 warp tile of m16n8k8 TF32 MMAs.
#define ASTRIDE 36    // 32 cols + pad: fragment LDS bank = (4g+tg) -> conflict-free
#define BSTRIDE 136   // 128 cols + pad: fragment LDS bank = (8tg+g) -> conflict-free

__device__ __forceinline__ unsigned f2tf(float x) {
    unsigned u;
    asm("cvt.rna.tf32.f32 %0, %1;" : "=r"(u) : "f"(x));
    return u;
}

__global__ __launch_bounds__(256) void tgemm_kernel(
        const float* __restrict__ A, const float* __restrict__ Bm,
        float* __restrict__ Cm, const float* __restrict__ bias,
        const float* __restrict__ res, int M, int N, int K, int relu) {
    __shared__ unsigned As[128 * ASTRIDE];
    __shared__ unsigned Bs[32 * BSTRIDE];
    int tid = threadIdx.x;
    int wid = tid >> 5, lane = tid & 31;
    int g = lane >> 2, tg = lane & 3;
    int wm = (wid >> 2) * 64;      // 0 / 64
    int wn = (wid & 3) * 32;       // 0,32,64,96

    const float* Ap = A + (size_t)(blockIdx.y * 128) * K;
    const float* Bp = Bm + (size_t)blockIdx.x * 128;

    float acc[4][4][4];
    #pragma unroll
    for (int i = 0; i < 4; i++)
        #pragma unroll
        for (int j = 0; j < 4; j++)
            #pragma unroll
            for (int r = 0; r < 4; r++) acc[i][j][r] = 0.f;

    int arow = tid >> 3;            // 0..31
    int acol = (tid & 7) * 4;       // 0..28
    int brow = tid >> 5;            // 0..7
    int bcol = (tid & 31) * 4;      // 0..124

    for (int k0 = 0; k0 < K; k0 += 32) {
        #pragma unroll
        for (int p = 0; p < 4; p++) {
            float4 v = *(const float4*)(Ap + (size_t)(arow + p * 32) * K + k0 + acol);
            uint4 u = make_uint4(f2tf(v.x), f2tf(v.y), f2tf(v.z), f2tf(v.w));
            *(uint4*)(As + (arow + p * 32) * ASTRIDE + acol) = u;
        }
        #pragma unroll
        for (int p = 0; p < 4; p++) {
            float4 v = *(const float4*)(Bp + (size_t)(k0 + brow + p * 8) * N + bcol);
            uint4 u = make_uint4(f2tf(v.x), f2tf(v.y), f2tf(v.z), f2tf(v.w));
            *(uint4*)(Bs + (brow + p * 8) * BSTRIDE + bcol) = u;
        }
        __syncthreads();

        #pragma unroll
        for (int kk = 0; kk < 32; kk += 8) {
            unsigned af[4][4], bf[4][2];
            #pragma unroll
            for (int i = 0; i < 4; i++) {
                int r = wm + i * 16 + g;
                af[i][0] = As[r * ASTRIDE + kk + tg];
                af[i][1] = As[(r + 8) * ASTRIDE + kk + tg];
                af[i][2] = As[r * ASTRIDE + kk + tg + 4];
                af[i][3] = As[(r + 8) * ASTRIDE + kk + tg + 4];
            }
            #pragma unroll
            for (int j = 0; j < 4; j++) {
                int c = wn + j * 8 + g;
                bf[j][0] = Bs[(kk + tg) * BSTRIDE + c];
                bf[j][1] = Bs[(kk + tg + 4) * BSTRIDE + c];
            }
            #pragma unroll
            for (int i = 0; i < 4; i++)
                #pragma unroll
                for (int j = 0; j < 4; j++) {
                    asm volatile(
                        "mma.sync.aligned.m16n8k8.row.col.f32.tf32.tf32.f32 "
                        "{%0,%1,%2,%3}, {%4,%5,%6,%7}, {%8,%9}, {%0,%1,%2,%3};"
                        : "+f"(acc[i][j][0]), "+f"(acc[i][j][1]),
                          "+f"(acc[i][j][2]), "+f"(acc[i][j][3])
                        : "r"(af[i][0]), "r"(af[i][1]), "r"(af[i][2]), "r"(af[i][3]),
                          "r"(bf[j][0]), "r"(bf[j][1]));
                }
        }
        __syncthreads();
    }

    // epilogue
    int gm0 = blockIdx.y * 128 + wm;
    int gn0 = blockIdx.x * 128 + wn;
    #pragma unroll
    for (int i = 0; i < 4; i++) {
        #pragma unroll
        for (int j = 0; j < 4; j++) {
            int row = gm0 + i * 16 + g;
            int col = gn0 + j * 8 + tg * 2;
            float b0 = 0.f, b1 = 0.f;
            if (bias) { b0 = bias[col]; b1 = bias[col + 1]; }
            #pragma unroll
            for (int half = 0; half < 2; half++) {
                int r = row + half * 8;
                size_t off = (size_t)r * N + col;
                float v0 = acc[i][j][half * 2 + 0] + b0;
                float v1 = acc[i][j][half * 2 + 1] + b1;
                if (relu) { v0 = fmaxf(v0, 0.f); v1 = fmaxf(v1, 0.f); }
                if (res)  { v0 += res[off]; v1 += res[off + 1]; }
                *(float2*)(Cm + off) = make_float2(v0, v1);
            }
        }
    }
}

// ---------------- attention scores: S[b,h,t,s] = q.k (raw, causal tiles only)
__global__ void scores_kernel(const float* __restrict__ qkv, float* __restrict__ w) {
    int st = blockIdx.x, tt = blockIdx.y, z = blockIdx.z;
    if (st > tt) return;                           // fully-masked tile
    int b = z / HN, h = z % HN;
    int t0 = tt * 64, s0 = st * 64;
    __shared__ float qs[64][65], ks[64][65];
    int tid = threadIdx.x;
    #pragma unroll
    for (int i = 0; i < 16; i++) {
        int idx = tid + i * 256;
        int r = idx >> 6, d = idx & 63;
        qs[r][d] = qkv[((size_t)(b * TN + t0 + r)) * QKVN + h * DN + d];
        ks[r][d] = qkv[((size_t)(b * TN + s0 + r)) * QKVN + CN + h * DN + d];
    }
    __syncthreads();
    int trow = (tid >> 4) << 2, tcol = (tid & 15) << 2;
    float acc[4][4] = {};
    #pragma unroll
    for (int d = 0; d < 64; d++) {
        float a[4], bb[4];
        #pragma unroll
        for (int i = 0; i < 4; i++) a[i] = qs[trow + i][d];
        #pragma unroll
        for (int j = 0; j < 4; j++) bb[j] = ks[tcol + j][d];
        #pragma unroll
        for (int i = 0; i < 4; i++)
            #pragma unroll
            for (int j = 0; j < 4; j++) acc[i][j] = fmaf(a[i], bb[j], acc[i][j]);
    }
    size_t base = (size_t)z * TN * TN;
    #pragma unroll
    for (int i = 0; i < 4; i++)
        #pragma unroll
        for (int j = 0; j < 4; j++)
            w[base + (size_t)(t0 + trow + i) * TN + s0 + tcol + j] = acc[i][j];
}

// ---------------- causal softmax in-place over rows of g_w ------------------
__global__ void softmax_kernel(float* __restrict__ w) {
    int row = blockIdx.x;            // 0 .. B*H*T-1
    int t = row % TN;
    float* wr = w + (size_t)row * TN;
    int n = t + 1;
    int tid = threadIdx.x;           // 128 threads
    const float scale = rsqrtf((float)CN);
    __shared__ float sred[32];

    float mx = -1e30f;
    for (int s = tid; s < n; s += 128) mx = fmaxf(mx, wr[s]);
    #pragma unroll
    for (int o = 16; o; o >>= 1) mx = fmaxf(mx, __shfl_xor_sync(0xffffffffu, mx, o));
    if ((tid & 31) == 0) sred[tid >> 5] = mx;
    __syncthreads();
    if (tid < 32) {
        float v = (tid < 4) ? sred[tid] : -1e30f;
        #pragma unroll
        for (int o = 2; o; o >>= 1) v = fmaxf(v, __shfl_xor_sync(0xffffffffu, v, o));
        if (tid == 0) sred[0] = v;
    }
    __syncthreads();
    float m = sred[0];
    __syncthreads();

    float sum = 0.f;
    for (int s = tid; s < n; s += 128) {
        float e = __expf(scale * (wr[s] - m));
        wr[s] = e;
        sum += e;
    }
    #pragma unroll
    for (int o = 16; o; o >>= 1) sum += __shfl_xor_sync(0xffffffffu, sum, o);
    if ((tid & 31) == 0) sred[tid >> 5] = sum;
    __syncthreads();
    if (tid < 32) {
        float v = (tid < 4) ? sred[tid] : 0.f;
        #pragma unroll
        for (int o = 2; o; o >>= 1) v += __shfl_xor_sync(0xffffffffu, v, o);
        if (tid == 0) sred[0] = v;
    }
    __syncthreads();
    float inv = 1.f / sred[0];
    for (int s = tid; s < n; s += 128) wr[s] *= inv;
    for (int s = n + tid; s < TN; s += 128) wr[s] = 0.f;
}

// ---------------- O = P @ V, writes (B,T,H*D) layout -------------------------
__global__ void wv_kernel(const float* __restrict__ qkv, const float* __restrict__ w,
                          float* __restrict__ att) {
    int tt = blockIdx.x, z = blockIdx.z;
    int b = z / HN, h = z % HN;
    int t0 = tt * 64;
    __shared__ float ws[64][65], vs[64][65];
    int tid = threadIdx.x;
    int trow = (tid >> 4) << 2, tcol = (tid & 15) << 2;
    float acc[4][4] = {};
    for (int st = 0; st <= tt; st++) {     // causal: only s-tiles <= t-tile
        int s0 = st * 64;
        #pragma unroll
        for (int i = 0; i < 16; i++) {
            int idx = tid + i * 256;
            int r = idx >> 6, cc = idx & 63;
            ws[r][cc] = w[((size_t)z * TN + t0 + r) * TN + s0 + cc];
            vs[r][cc] = qkv[((size_t)(b * TN + s0 + r)) * QKVN + 2 * CN + h * DN + cc];
        }
        __syncthreads();
        #pragma unroll
        for (int ss = 0; ss < 64; ss++) {
            float a[4], bb[4];
            #pragma unroll
            for (int i = 0; i < 4; i++) a[i] = ws[trow + i][ss];
            #pragma unroll
            for (int j = 0; j < 4; j++) bb[j] = vs[ss][tcol + j];
            #pragma unroll
            for (int i = 0; i < 4; i++)
                #pragma unroll
                for (int j = 0; j < 4; j++) acc[i][j] = fmaf(a[i], bb[j], acc[i][j]);
        }
        __syncthreads();
    }
    #pragma unroll
    for (int i = 0; i < 4; i++)
        #pragma unroll
        for (int j = 0; j < 4; j++)
            att[((size_t)(b * TN + t0 + trow + i)) * CN + h * DN + tcol + j] = acc[i][j];
}

// ---------------- host orchestration ----------------------------------------
extern "C" void kernel_launch(void* const* d_in, const int* in_sizes, int n_in,
                              void* d_out, int out_size) {
    const int*   x       = (const int*)  d_in[0];
    const float* tok_emb = (const float*)d_in[1];
    const float* pos_emb = (const float*)d_in[2];
    const float* Wq      = (const float*)d_in[3];
    const float* Wk      = (const float*)d_in[4];
    const float* Wv      = (const float*)d_in[5];
    const float* Wo      = (const float*)d_in[6];
    const float* bo      = (const float*)d_in[7];
    const float* ln1_g   = (const float*)d_in[8];
    const float* ln1_b   = (const float*)d_in[9];
    const float* ln2_g   = (const float*)d_in[10];
    const float* ln2_b   = (const float*)d_in[11];
    const float* W1      = (const float*)d_in[12];
    const float* b1      = (const float*)d_in[13];
    const float* W2      = (const float*)d_in[14];
    const float* b2      = (const float*)d_in[15];
    const float* lnf_g   = (const float*)d_in[16];
    const float* lnf_b   = (const float*)d_in[17];
    const float* Wh      = (const float*)d_in[18];
    const float* bh      = (const float*)d_in[19];
    float* out = (float*)d_out;

    float *ph, *pain, *pqkv, *pw, *patt, *pffn, *pwt;
    cudaGetSymbolAddress((void**)&ph,   g_h);
    cudaGetSymbolAddress((void**)&pain, g_ain);
    cudaGetSymbolAddress((void**)&pqkv, g_qkv);
    cudaGetSymbolAddress((void**)&pw,   g_w);
    cudaGetSymbolAddress((void**)&patt, g_att);
    cudaGetSymbolAddress((void**)&pffn, g_ffn);
    cudaGetSymbolAddress((void**)&pwt,  g_wt);

    const int HCD = HN * CN * DN;

    embed_kernel<<<(BT * CN + 255) / 256, 256>>>(x, tok_emb, pos_emb, ph);

    for (int l = 0; l < LN; l++) {
        layernorm_kernel<<<BT, 256>>>(ph, ln1_g + l * CN, ln1_b + l * CN, pain);
        transpose_qkv_kernel<<<(3 * HCD + 255) / 256, 256>>>(
            Wq + (size_t)l * HCD, Wk + (size_t)l * HCD, Wv + (size_t)l * HCD, pwt);
        tgemm_kernel<<<dim3(QKVN / 128, BT / 128), 256>>>(
            pain, pwt, pqkv, nullptr, nullptr, BT, QKVN, CN, 0);
        scores_kernel<<<dim3(TN / 64, TN / 64, BN_ * HN), 256>>>(pqkv, pw);
        softmax_kernel<<<BN_ * HN * TN, 128>>>(pw);
        wv_kernel<<<dim3(TN / 64, 1, BN_ * HN), 256>>>(pqkv, pw, patt);
        tgemm_kernel<<<dim3(CN / 128, BT / 128), 256>>>(
            patt, Wo + (size_t)l * CN * CN, ph, bo + l * CN, ph, BT, CN, CN, 0);
        layernorm_kernel<<<BT, 256>>>(ph, ln2_g + l * CN, ln2_b + l * CN, pain);
        tgemm_kernel<<<dim3(FN / 128, BT / 128), 256>>>(
            pain, W1 + (size_t)l * CN * FN, pffn, b1 + l * FN, nullptr, BT, FN, CN, 1);
        tgemm_kernel<<<dim3(CN / 128, BT / 128), 256>>>(
            pffn, W2 + (size_t)l * FN * CN, ph, b2 + l * CN, ph, BT, CN, FN, 0);
    }

    layernorm_kernel<<<BT, 256>>>(ph, lnf_g, lnf_b, pain);
    tgemm_kernel<<<dim3(VN / 128, BT / 128), 256>>>(
        pain, Wh, out, bh, nullptr, BT, VN, CN, 0);
}

// round 9
// speedup vs baseline: 3.0474x; 1.4901x over previous
#include <cuda_runtime.h>
#include <math.h>

// Problem constants
#define LN   6
#define HN   12
#define DN   64
#define CN   768
#define VN   32000
#define BN_  2
#define TN   1024
#define BT   2048          // B*T
#define FN   3072          // 4*C
#define QKVN 2304          // 3*C

// ---------------- scratch (device globals; no allocations allowed) ----------
__device__ float g_h   [BT * CN];                       // residual stream
__device__ float g_ain [BT * CN];                       // layernorm output
__device__ float g_qkv [BT * QKVN];                     // fused q|k|v
__device__ float g_att [BT * CN];                       // attention output (B,T,H*D)
__device__ float g_ffn [BT * FN];                       // MLP hidden
__device__ float g_wt  [CN * QKVN];                     // transposed qkv weights (C x 3C)

// ---------------- embedding -------------------------------------------------
__global__ void embed_kernel(const int* __restrict__ x, const float* __restrict__ tok,
                             const float* __restrict__ pos, float* __restrict__ out) {
    int idx = blockIdx.x * 256 + threadIdx.x;
    if (idx >= BT * CN) return;
    int bt = idx / CN, c = idx % CN;
    int t = bt % TN;
    out[idx] = tok[(size_t)x[bt] * CN + c] + pos[t * CN + c];
}

// ---------------- weight transpose: (H,C,D)x3 -> (C, 3*H*D) -----------------
__global__ void transpose_qkv_kernel(const float* __restrict__ Wq, const float* __restrict__ Wk,
                                     const float* __restrict__ Wv, float* __restrict__ out) {
    int idx = blockIdx.x * 256 + threadIdx.x;
    const int per = HN * CN * DN;
    if (idx >= 3 * per) return;
    int which = idx / per, r = idx % per;
    int h = r / (CN * DN);
    int c = (r / DN) % CN;
    int d = r % DN;
    const float* W = (which == 0) ? Wq : (which == 1) ? Wk : Wv;
    out[c * QKVN + which * CN + h * DN + d] = W[(size_t)(h * CN + c) * DN + d];
}

// ---------------- layernorm (one block of 256 per row, C=768) ---------------
__global__ void layernorm_kernel(const float* __restrict__ x, const float* __restrict__ g,
                                 const float* __restrict__ b, float* __restrict__ out) {
    int row = blockIdx.x;
    const float* xr = x + (size_t)row * CN;
    float* orow = out + (size_t)row * CN;
    int tid = threadIdx.x;
    __shared__ float sred[32];

    float s = 0.f;
    for (int c = tid; c < CN; c += 256) s += xr[c];
    #pragma unroll
    for (int o = 16; o; o >>= 1) s += __shfl_xor_sync(0xffffffffu, s, o);
    if ((tid & 31) == 0) sred[tid >> 5] = s;
    __syncthreads();
    if (tid < 32) {
        float v = (tid < 8) ? sred[tid] : 0.f;
        #pragma unroll
        for (int o = 4; o; o >>= 1) v += __shfl_xor_sync(0xffffffffu, v, o);
        if (tid == 0) sred[0] = v;
    }
    __syncthreads();
    float mean = sred[0] * (1.0f / CN);
    __syncthreads();

    float vs = 0.f;
    for (int c = tid; c < CN; c += 256) { float d = xr[c] - mean; vs += d * d; }
    #pragma unroll
    for (int o = 16; o; o >>= 1) vs += __shfl_xor_sync(0xffffffffu, vs, o);
    if ((tid & 31) == 0) sred[tid >> 5] = vs;
    __syncthreads();
    if (tid < 32) {
        float v = (tid < 8) ? sred[tid] : 0.f;
        #pragma unroll
        for (int o = 4; o; o >>= 1) v += __shfl_xor_sync(0xffffffffu, v, o);
        if (tid == 0) sred[0] = v;
    }
    __syncthreads();
    float inv = rsqrtf(sred[0] * (1.0f / CN) + 1e-5f);
    for (int c = tid; c < CN; c += 256)
        orow[c] = (xr[c] - mean) * inv * g[c] + b[c];
}

// ---------------- TF32 tensor-core GEMM, cp.async 2-stage pipeline ----------
// C = A(MxK) @ B(KxN) [+bias][relu][+res]; M%128==0, N%128==0, K%16==0.
// CTA tile 128x128x16 per stage; 8 warps, each 64x32 warp tile, m16n8k8 TF32.
#define AST 20    // 16 cols + pad: fragment LDS bank = perm(g*20+tg) -> conflict-free
#define BST 136   // 128 cols + pad: fragment LDS bank = (8tg+g) -> conflict-free
#define KCH 16

__device__ __forceinline__ unsigned f2tf(float x) {
    unsigned u;
    asm("cvt.rna.tf32.f32 %0, %1;" : "=r"(u) : "f"(x));
    return u;
}

__global__ __launch_bounds__(256) void tgemm_kernel(
        const float* __restrict__ A, const float* __restrict__ Bm,
        float* __restrict__ Cm, const float* __restrict__ bias,
        const float* __restrict__ res, int M, int N, int K, int relu) {
    __shared__ float As[2][128 * AST];
    __shared__ float Bs[2][16 * BST];
    int tid = threadIdx.x;
    int wid = tid >> 5, lane = tid & 31;
    int g = lane >> 2, tg = lane & 3;
    int wm = (wid >> 2) * 64;      // 0 / 64
    int wn = (wid & 3) * 32;       // 0,32,64,96

    const float* Ap = A + (size_t)(blockIdx.y * 128) * K;
    const float* Bp = Bm + (size_t)blockIdx.x * 128;

    float acc[4][4][4];
    #pragma unroll
    for (int i = 0; i < 4; i++)
        #pragma unroll
        for (int j = 0; j < 4; j++)
            #pragma unroll
            for (int r = 0; r < 4; r++) acc[i][j][r] = 0.f;

    // cp.async thread mapping: A tile 128x16 (2 float4/thread), B tile 16x128 (2 float4/thread)
    int a_r0 = tid >> 2;            // 0..63 (second: +64)
    int a_c  = (tid & 3) * 4;       // 0,4,8,12
    int b_r0 = tid >> 5;            // 0..7  (second: +8)
    int b_c  = (tid & 31) * 4;      // 0..124

    unsigned abase0 = (unsigned)__cvta_generic_to_shared(&As[0][0]);
    unsigned abase1 = (unsigned)__cvta_generic_to_shared(&As[1][0]);
    unsigned bbase0 = (unsigned)__cvta_generic_to_shared(&Bs[0][0]);
    unsigned bbase1 = (unsigned)__cvta_generic_to_shared(&Bs[1][0]);
    unsigned a_off0 = (unsigned)((a_r0 * AST + a_c) * 4);
    unsigned a_off1 = (unsigned)(((a_r0 + 64) * AST + a_c) * 4);
    unsigned b_off0 = (unsigned)((b_r0 * BST + b_c) * 4);
    unsigned b_off1 = (unsigned)(((b_r0 + 8) * BST + b_c) * 4);

#define ISSUE_STAGE(KT, BUF) do {                                                          \
    unsigned ab_ = (BUF) ? abase1 : abase0;                                                \
    unsigned bb_ = (BUF) ? bbase1 : bbase0;                                                \
    const float* ap_ = Ap + (KT) * KCH;                                                    \
    const float* bp_ = Bp + (size_t)((KT) * KCH) * N;                                      \
    asm volatile("cp.async.ca.shared.global [%0], [%1], 16;" ::                            \
                 "r"(ab_ + a_off0), "l"(ap_ + (size_t)a_r0 * K + a_c));                    \
    asm volatile("cp.async.ca.shared.global [%0], [%1], 16;" ::                            \
                 "r"(ab_ + a_off1), "l"(ap_ + (size_t)(a_r0 + 64) * K + a_c));             \
    asm volatile("cp.async.ca.shared.global [%0], [%1], 16;" ::                            \
                 "r"(bb_ + b_off0), "l"(bp_ + (size_t)b_r0 * N + b_c));                    \
    asm volatile("cp.async.ca.shared.global [%0], [%1], 16;" ::                            \
                 "r"(bb_ + b_off1), "l"(bp_ + (size_t)(b_r0 + 8) * N + b_c));              \
    asm volatile("cp.async.commit_group;");                                                \
} while (0)

    int NT = K / KCH;
    ISSUE_STAGE(0, 0);

    for (int kt = 0; kt < NT; kt++) {
        int buf = kt & 1;
        if (kt + 1 < NT) {
            ISSUE_STAGE(kt + 1, (kt + 1) & 1);
            asm volatile("cp.async.wait_group 1;");
        } else {
            asm volatile("cp.async.wait_group 0;");
        }
        __syncthreads();

        const float* as = As[buf];
        const float* bs = Bs[buf];
        #pragma unroll
        for (int kk = 0; kk < KCH; kk += 8) {
            unsigned af[4][4], bf[4][2];
            #pragma unroll
            for (int i = 0; i < 4; i++) {
                int r = wm + i * 16 + g;
                af[i][0] = f2tf(as[r * AST + kk + tg]);
                af[i][1] = f2tf(as[(r + 8) * AST + kk + tg]);
                af[i][2] = f2tf(as[r * AST + kk + tg + 4]);
                af[i][3] = f2tf(as[(r + 8) * AST + kk + tg + 4]);
            }
            #pragma unroll
            for (int j = 0; j < 4; j++) {
                int c = wn + j * 8 + g;
                bf[j][0] = f2tf(bs[(kk + tg) * BST + c]);
                bf[j][1] = f2tf(bs[(kk + tg + 4) * BST + c]);
            }
            #pragma unroll
            for (int i = 0; i < 4; i++)
                #pragma unroll
                for (int j = 0; j < 4; j++) {
                    asm volatile(
                        "mma.sync.aligned.m16n8k8.row.col.f32.tf32.tf32.f32 "
                        "{%0,%1,%2,%3}, {%4,%5,%6,%7}, {%8,%9}, {%0,%1,%2,%3};"
                        : "+f"(acc[i][j][0]), "+f"(acc[i][j][1]),
                          "+f"(acc[i][j][2]), "+f"(acc[i][j][3])
                        : "r"(af[i][0]), "r"(af[i][1]), "r"(af[i][2]), "r"(af[i][3]),
                          "r"(bf[j][0]), "r"(bf[j][1]));
                }
        }
        __syncthreads();
    }
#undef ISSUE_STAGE

    // epilogue
    int gm0 = blockIdx.y * 128 + wm;
    int gn0 = blockIdx.x * 128 + wn;
    #pragma unroll
    for (int i = 0; i < 4; i++) {
        #pragma unroll
        for (int j = 0; j < 4; j++) {
            int row = gm0 + i * 16 + g;
            int col = gn0 + j * 8 + tg * 2;
            float b0 = 0.f, b1 = 0.f;
            if (bias) { b0 = bias[col]; b1 = bias[col + 1]; }
            #pragma unroll
            for (int half = 0; half < 2; half++) {
                int r = row + half * 8;
                size_t off = (size_t)r * N + col;
                float v0 = acc[i][j][half * 2 + 0] + b0;
                float v1 = acc[i][j][half * 2 + 1] + b1;
                if (relu) { v0 = fmaxf(v0, 0.f); v1 = fmaxf(v1, 0.f); }
                if (res)  { v0 += res[off]; v1 += res[off + 1]; }
                *(float2*)(Cm + off) = make_float2(v0, v1);
            }
        }
    }
}

// ---------------- fused flash attention (fp32) -------------------------------
// One block per (z = b*H+h, 64-row q tile). Online softmax over 32-wide s tiles.
// Thread layout: group g = tid>>4 owns rows trow..trow+3 in S, P and O tiles;
// row stats (m, l) live replicated in the 16 threads of each group.
__global__ __launch_bounds__(256) void flash_kernel(const float* __restrict__ qkv,
                                                    float* __restrict__ att) {
    int tt = blockIdx.x, z = blockIdx.z;
    int b = z / HN, h = z % HN;
    int t0 = tt * 64;
    __shared__ float qs[64][65];
    __shared__ float ks[32][65];
    __shared__ float vs[32][65];
    __shared__ float ps[64][33];
    int tid = threadIdx.x;
    int g = tid >> 4;           // 0..15 row group
    int c = tid & 15;           // 0..15
    int trow = g * 4;
    const float scale = rsqrtf((float)CN);

    for (int i = tid; i < 64 * 64; i += 256) {
        int r = i >> 6, d = i & 63;
        qs[r][d] = qkv[((size_t)(b * TN + t0 + r)) * QKVN + h * DN + d];
    }

    float m[4], l[4], acc[4][4];
    #pragma unroll
    for (int i = 0; i < 4; i++) {
        m[i] = -1e30f; l[i] = 0.f;
        #pragma unroll
        for (int j = 0; j < 4; j++) acc[i][j] = 0.f;
    }

    int nS = (t0 + 64) / 32;
    for (int st = 0; st < nS; st++) {
        int s0 = st * 32;
        __syncthreads();                 // previous PV done before reloading ks/vs
        for (int i = tid; i < 32 * 64; i += 256) {
            int r = i >> 6, d = i & 63;
            size_t base = ((size_t)(b * TN + s0 + r)) * QKVN + h * DN + d;
            ks[r][d] = qkv[base + CN];
            vs[r][d] = qkv[base + 2 * CN];
        }
        __syncthreads();

        // S tile: rows trow+i, cols c*2+j
        float s[4][2];
        #pragma unroll
        for (int i = 0; i < 4; i++) { s[i][0] = 0.f; s[i][1] = 0.f; }
        #pragma unroll 8
        for (int d = 0; d < 64; d++) {
            float k0 = ks[c * 2][d], k1 = ks[c * 2 + 1][d];
            #pragma unroll
            for (int i = 0; i < 4; i++) {
                float qv = qs[trow + i][d];
                s[i][0] = fmaf(qv, k0, s[i][0]);
                s[i][1] = fmaf(qv, k1, s[i][1]);
            }
        }
        #pragma unroll
        for (int i = 0; i < 4; i++) {
            int srow = t0 + trow + i;
            #pragma unroll
            for (int j = 0; j < 2; j++) {
                int scol = s0 + c * 2 + j;
                s[i][j] = (scol <= srow) ? s[i][j] * scale : -1e30f;
            }
        }

        // online softmax update per row
        float fac[4];
        #pragma unroll
        for (int i = 0; i < 4; i++) {
            float tm = fmaxf(s[i][0], s[i][1]);
            #pragma unroll
            for (int o = 1; o < 16; o <<= 1)
                tm = fmaxf(tm, __shfl_xor_sync(0xffffffffu, tm, o));
            float mn = fmaxf(m[i], tm);
            fac[i] = __expf(m[i] - mn);
            m[i] = mn;
            float p0 = __expf(s[i][0] - mn);
            float p1 = __expf(s[i][1] - mn);
            ps[trow + i][c * 2 + 0] = p0;
            ps[trow + i][c * 2 + 1] = p1;
            float rs = p0 + p1;
            #pragma unroll
            for (int o = 1; o < 16; o <<= 1)
                rs += __shfl_xor_sync(0xffffffffu, rs, o);
            l[i] = l[i] * fac[i] + rs;
        }
        #pragma unroll
        for (int i = 0; i < 4; i++)
            #pragma unroll
            for (int j = 0; j < 4; j++) acc[i][j] *= fac[i];
        __syncthreads();

        // PV: acc[i][j] += sum_ss ps[trow+i][ss] * vs[ss][c*4+j]
        #pragma unroll 8
        for (int ss = 0; ss < 32; ss++) {
            float pv0 = ps[trow + 0][ss], pv1 = ps[trow + 1][ss];
            float pv2 = ps[trow + 2][ss], pv3 = ps[trow + 3][ss];
            #pragma unroll
            for (int j = 0; j < 4; j++) {
                float vv = vs[ss][c * 4 + j];
                acc[0][j] = fmaf(pv0, vv, acc[0][j]);
                acc[1][j] = fmaf(pv1, vv, acc[1][j]);
                acc[2][j] = fmaf(pv2, vv, acc[2][j]);
                acc[3][j] = fmaf(pv3, vv, acc[3][j]);
            }
        }
    }

    #pragma unroll
    for (int i = 0; i < 4; i++) {
        float inv = 1.f / l[i];
        float4 o4 = make_float4(acc[i][0] * inv, acc[i][1] * inv,
                                acc[i][2] * inv, acc[i][3] * inv);
        *(float4*)(att + ((size_t)(b * TN + t0 + trow + i)) * CN + h * DN + c * 4) = o4;
    }
}

// ---------------- host orchestration ----------------------------------------
extern "C" void kernel_launch(void* const* d_in, const int* in_sizes, int n_in,
                              void* d_out, int out_size) {
    const int*   x       = (const int*)  d_in[0];
    const float* tok_emb = (const float*)d_in[1];
    const float* pos_emb = (const float*)d_in[2];
    const float* Wq      = (const float*)d_in[3];
    const float* Wk      = (const float*)d_in[4];
    const float* Wv      = (const float*)d_in[5];
    const float* Wo      = (const float*)d_in[6];
    const float* bo      = (const float*)d_in[7];
    const float* ln1_g   = (const float*)d_in[8];
    const float* ln1_b   = (const float*)d_in[9];
    const float* ln2_g   = (const float*)d_in[10];
    const float* ln2_b   = (const float*)d_in[11];
    const float* W1      = (const float*)d_in[12];
    const float* b1      = (const float*)d_in[13];
    const float* W2      = (const float*)d_in[14];
    const float* b2      = (const float*)d_in[15];
    const float* lnf_g   = (const float*)d_in[16];
    const float* lnf_b   = (const float*)d_in[17];
    const float* Wh      = (const float*)d_in[18];
    const float* bh      = (const float*)d_in[19];
    float* out = (float*)d_out;

    float *ph, *pain, *pqkv, *patt, *pffn, *pwt;
    cudaGetSymbolAddress((void**)&ph,   g_h);
    cudaGetSymbolAddress((void**)&pain, g_ain);
    cudaGetSymbolAddress((void**)&pqkv, g_qkv);
    cudaGetSymbolAddress((void**)&patt, g_att);
    cudaGetSymbolAddress((void**)&pffn, g_ffn);
    cudaGetSymbolAddress((void**)&pwt,  g_wt);

    const int HCD = HN * CN * DN;

    embed_kernel<<<(BT * CN + 255) / 256, 256>>>(x, tok_emb, pos_emb, ph);

    for (int l = 0; l < LN; l++) {
        layernorm_kernel<<<BT, 256>>>(ph, ln1_g + l * CN, ln1_b + l * CN, pain);
        transpose_qkv_kernel<<<(3 * HCD + 255) / 256, 256>>>(
            Wq + (size_t)l * HCD, Wk + (size_t)l * HCD, Wv + (size_t)l * HCD, pwt);
        tgemm_kernel<<<dim3(QKVN / 128, BT / 128), 256>>>(
            pain, pwt, pqkv, nullptr, nullptr, BT, QKVN, CN, 0);
        flash_kernel<<<dim3(TN / 64, 1, BN_ * HN), 256>>>(pqkv, patt);
        tgemm_kernel<<<dim3(CN / 128, BT / 128), 256>>>(
            patt, Wo + (size_t)l * CN * CN, ph, bo + l * CN, ph, BT, CN, CN, 0);
        layernorm_kernel<<<BT, 256>>>(ph, ln2_g + l * CN, ln2_b + l * CN, pain);
        tgemm_kernel<<<dim3(FN / 128, BT / 128), 256>>>(
            pain, W1 + (size_t)l * CN * FN, pffn, b1 + l * FN, nullptr, BT, FN, CN, 1);
        tgemm_kernel<<<dim3(CN / 128, BT / 128), 256>>>(
            pffn, W2 + (size_t)l * FN * CN, ph, b2 + l * CN, ph, BT, CN, FN, 0);
    }

    layernorm_kernel<<<BT, 256>>>(ph, lnf_g, lnf_b, pain);
    tgemm_kernel<<<dim3(VN / 128, BT / 128), 256>>>(
        pain, Wh, out, bh, nullptr, BT, VN, CN, 0);
}

// round 10
// speedup vs baseline: 3.3634x; 1.1037x over previous
#include <cuda_runtime.h>
#include <math.h>

// Problem constants
#define LN   6
#define HN   12
#define DN   64
#define CN   768
#define VN   32000
#define BN_  2
#define TN   1024
#define BT   2048          // B*T
#define FN   3072          // 4*C
#define QKVN 2304          // 3*C

// ---------------- scratch (device globals; no allocations allowed) ----------
__device__ float g_h   [BT * CN];                       // residual stream
__device__ float g_ain [BT * CN];                       // layernorm output (tf32-rounded)
__device__ float g_qkv [BT * QKVN];                     // fused q|k|v
__device__ float g_att [BT * CN];                       // attention output (tf32-rounded)
__device__ float g_ffn [BT * FN];                       // MLP hidden (tf32-rounded)
__device__ float g_wt  [CN * QKVN];                     // transposed qkv weights (tf32)
__device__ float g_woc [LN * CN * CN];                  // tf32 copies of weights
__device__ float g_w1c [LN * CN * FN];
__device__ float g_w2c [LN * FN * CN];
__device__ float g_whc [CN * VN];

__device__ __forceinline__ unsigned f2tf(float x) {
    unsigned u;
    asm("cvt.rna.tf32.f32 %0, %1;" : "=r"(u) : "f"(x));
    return u;
}
__device__ __forceinline__ float f2tf_f(float x) { return __uint_as_float(f2tf(x)); }

// ---------------- tf32 pre-conversion (vectorized) ---------------------------
__global__ void cvtf_kernel(const float4* __restrict__ src, float4* __restrict__ dst, int n4) {
    int i = blockIdx.x * 256 + threadIdx.x;
    if (i >= n4) return;
    float4 v = src[i];
    dst[i] = make_float4(f2tf_f(v.x), f2tf_f(v.y), f2tf_f(v.z), f2tf_f(v.w));
}

// ---------------- embedding -------------------------------------------------
__global__ void embed_kernel(const int* __restrict__ x, const float* __restrict__ tok,
                             const float* __restrict__ pos, float* __restrict__ out) {
    int idx = blockIdx.x * 256 + threadIdx.x;
    if (idx >= BT * CN) return;
    int bt = idx / CN, c = idx % CN;
    int t = bt % TN;
    out[idx] = tok[(size_t)x[bt] * CN + c] + pos[t * CN + c];
}

// ---------------- weight transpose: (H,C,D)x3 -> (C, 3*H*D), tf32-rounded ---
__global__ void transpose_qkv_kernel(const float* __restrict__ Wq, const float* __restrict__ Wk,
                                     const float* __restrict__ Wv, float* __restrict__ out) {
    int idx = blockIdx.x * 256 + threadIdx.x;
    const int per = HN * CN * DN;
    if (idx >= 3 * per) return;
    int which = idx / per, r = idx % per;
    int h = r / (CN * DN);
    int c = (r / DN) % CN;
    int d = r % DN;
    const float* W = (which == 0) ? Wq : (which == 1) ? Wk : Wv;
    out[c * QKVN + which * CN + h * DN + d] = f2tf_f(W[(size_t)(h * CN + c) * DN + d]);
}

// ---------------- layernorm (tf32-rounded output: it only feeds GEMM A) -----
__global__ void layernorm_kernel(const float* __restrict__ x, const float* __restrict__ g,
                                 const float* __restrict__ b, float* __restrict__ out) {
    int row = blockIdx.x;
    const float* xr = x + (size_t)row * CN;
    float* orow = out + (size_t)row * CN;
    int tid = threadIdx.x;
    __shared__ float sred[32];

    float s = 0.f;
    for (int c = tid; c < CN; c += 256) s += xr[c];
    #pragma unroll
    for (int o = 16; o; o >>= 1) s += __shfl_xor_sync(0xffffffffu, s, o);
    if ((tid & 31) == 0) sred[tid >> 5] = s;
    __syncthreads();
    if (tid < 32) {
        float v = (tid < 8) ? sred[tid] : 0.f;
        #pragma unroll
        for (int o = 4; o; o >>= 1) v += __shfl_xor_sync(0xffffffffu, v, o);
        if (tid == 0) sred[0] = v;
    }
    __syncthreads();
    float mean = sred[0] * (1.0f / CN);
    __syncthreads();

    float vs = 0.f;
    for (int c = tid; c < CN; c += 256) { float d = xr[c] - mean; vs += d * d; }
    #pragma unroll
    for (int o = 16; o; o >>= 1) vs += __shfl_xor_sync(0xffffffffu, vs, o);
    if ((tid & 31) == 0) sred[tid >> 5] = vs;
    __syncthreads();
    if (tid < 32) {
        float v = (tid < 8) ? sred[tid] : 0.f;
        #pragma unroll
        for (int o = 4; o; o >>= 1) v += __shfl_xor_sync(0xffffffffu, v, o);
        if (tid == 0) sred[0] = v;
    }
    __syncthreads();
    float inv = rsqrtf(sred[0] * (1.0f / CN) + 1e-5f);
    for (int c = tid; c < CN; c += 256)
        orow[c] = f2tf_f((xr[c] - mean) * inv * g[c] + b[c]);
}

// ---------------- TF32 tensor-core GEMM, cp.async 2-stage, KCH=32 -----------
// Inputs MUST be tf32-pre-rounded floats. C = A@B [+bias][relu->round][+res].
// M%128==0, N%128==0, K%32==0. Dynamic smem 71680B.
#define AST 36    // 32 cols + pad: A-frag banks (4g+tg) -> conflict-free
#define BST 136   // 128 cols + pad: B-frag banks (8tg+g) -> conflict-free
#define KCH 32
#define TG_SMEM ((2 * 128 * AST + 2 * 32 * BST) * 4)

__global__ __launch_bounds__(256) void tgemm_kernel(
        const float* __restrict__ A, const float* __restrict__ Bm,
        float* __restrict__ Cm, const float* __restrict__ bias,
        const float* __restrict__ res, int M, int N, int K, int relu) {
    extern __shared__ float dsm[];
    float* Asm = dsm;                       // [2][128*AST]
    float* Bsm = dsm + 2 * 128 * AST;       // [2][32*BST]
    int tid = threadIdx.x;
    int wid = tid >> 5, lane = tid & 31;
    int g = lane >> 2, tg = lane & 3;
    int wm = (wid >> 2) * 64;      // 0 / 64
    int wn = (wid & 3) * 32;       // 0,32,64,96

    const float* Ap = A + (size_t)(blockIdx.y * 128) * K;
    const float* Bp = Bm + (size_t)blockIdx.x * 128;

    float acc[4][4][4];
    #pragma unroll
    for (int i = 0; i < 4; i++)
        #pragma unroll
        for (int j = 0; j < 4; j++)
            #pragma unroll
            for (int r = 0; r < 4; r++) acc[i][j][r] = 0.f;

    // cp.async mapping: A tile 128x32 (4 float4/thread), B tile 32x128 (4 float4/thread)
    int a_r = tid >> 3;             // 0..31 (+32p)
    int a_c = (tid & 7) * 4;        // 0..28
    int b_r = tid >> 5;             // 0..7  (+8p)
    int b_c = (tid & 31) * 4;       // 0..124

    unsigned abase = (unsigned)__cvta_generic_to_shared(Asm);
    unsigned bbase = (unsigned)__cvta_generic_to_shared(Bsm);

#define ISSUE_STAGE(KT, BUF) do {                                                          \
    unsigned ab_ = abase + (unsigned)(BUF) * (128 * AST * 4);                              \
    unsigned bb_ = bbase + (unsigned)(BUF) * (32 * BST * 4);                               \
    const float* ap_ = Ap + (KT) * KCH;                                                    \
    const float* bp_ = Bp + (size_t)((KT) * KCH) * N;                                      \
    _Pragma("unroll")                                                                      \
    for (int p = 0; p < 4; p++)                                                            \
        asm volatile("cp.async.cg.shared.global [%0], [%1], 16;" ::                        \
            "r"(ab_ + (unsigned)(((a_r + p * 32) * AST + a_c) * 4)),                       \
            "l"(ap_ + (size_t)(a_r + p * 32) * K + a_c));                                  \
    _Pragma("unroll")                                                                      \
    for (int p = 0; p < 4; p++)                                                            \
        asm volatile("cp.async.cg.shared.global [%0], [%1], 16;" ::                        \
            "r"(bb_ + (unsigned)(((b_r + p * 8) * BST + b_c) * 4)),                        \
            "l"(bp_ + (size_t)(b_r + p * 8) * N + b_c));                                   \
    asm volatile("cp.async.commit_group;");                                                \
} while (0)

    int NT = K / KCH;
    ISSUE_STAGE(0, 0);

    for (int kt = 0; kt < NT; kt++) {
        int buf = kt & 1;
        if (kt + 1 < NT) {
            ISSUE_STAGE(kt + 1, (kt + 1) & 1);
            asm volatile("cp.async.wait_group 1;");
        } else {
            asm volatile("cp.async.wait_group 0;");
        }
        __syncthreads();

        const unsigned* as = (const unsigned*)(Asm + buf * 128 * AST);
        const unsigned* bs = (const unsigned*)(Bsm + buf * 32 * BST);
        #pragma unroll
        for (int kk = 0; kk < KCH; kk += 8) {
            unsigned af[4][4], bf[4][2];
            #pragma unroll
            for (int i = 0; i < 4; i++) {
                int r = wm + i * 16 + g;
                af[i][0] = as[r * AST + kk + tg];
                af[i][1] = as[(r + 8) * AST + kk + tg];
                af[i][2] = as[r * AST + kk + tg + 4];
                af[i][3] = as[(r + 8) * AST + kk + tg + 4];
            }
            #pragma unroll
            for (int j = 0; j < 4; j++) {
                int c = wn + j * 8 + g;
                bf[j][0] = bs[(kk + tg) * BST + c];
                bf[j][1] = bs[(kk + tg + 4) * BST + c];
            }
            #pragma unroll
            for (int i = 0; i < 4; i++)
                #pragma unroll
                for (int j = 0; j < 4; j++) {
                    asm volatile(
                        "mma.sync.aligned.m16n8k8.row.col.f32.tf32.tf32.f32 "
                        "{%0,%1,%2,%3}, {%4,%5,%6,%7}, {%8,%9}, {%0,%1,%2,%3};"
                        : "+f"(acc[i][j][0]), "+f"(acc[i][j][1]),
                          "+f"(acc[i][j][2]), "+f"(acc[i][j][3])
                        : "r"(af[i][0]), "r"(af[i][1]), "r"(af[i][2]), "r"(af[i][3]),
                          "r"(bf[j][0]), "r"(bf[j][1]));
                }
        }
        __syncthreads();
    }
#undef ISSUE_STAGE

    // epilogue; relu=1 also tf32-rounds the store (FC1 output feeds FC2's A)
    int gm0 = blockIdx.y * 128 + wm;
    int gn0 = blockIdx.x * 128 + wn;
    #pragma unroll
    for (int i = 0; i < 4; i++) {
        #pragma unroll
        for (int j = 0; j < 4; j++) {
            int row = gm0 + i * 16 + g;
            int col = gn0 + j * 8 + tg * 2;
            float b0 = 0.f, b1 = 0.f;
            if (bias) { b0 = bias[col]; b1 = bias[col + 1]; }
            #pragma unroll
            for (int half = 0; half < 2; half++) {
                int r = row + half * 8;
                size_t off = (size_t)r * N + col;
                float v0 = acc[i][j][half * 2 + 0] + b0;
                float v1 = acc[i][j][half * 2 + 1] + b1;
                if (relu) {
                    v0 = f2tf_f(fmaxf(v0, 0.f));
                    v1 = f2tf_f(fmaxf(v1, 0.f));
                }
                if (res)  { v0 += res[off]; v1 += res[off + 1]; }
                *(float2*)(Cm + off) = make_float2(v0, v1);
            }
        }
    }
}

// ---------------- fused flash attention (fp32), tf32-rounded output ----------
__global__ __launch_bounds__(256) void flash_kernel(const float* __restrict__ qkv,
                                                    float* __restrict__ att) {
    int tt = blockIdx.x, z = blockIdx.z;
    int b = z / HN, h = z % HN;
    int t0 = tt * 64;
    __shared__ float qs[64][65];
    __shared__ float ks[32][65];
    __shared__ float vs[32][65];
    __shared__ float ps[64][33];
    int tid = threadIdx.x;
    int g = tid >> 4;           // 0..15 row group
    int c = tid & 15;           // 0..15
    int trow = g * 4;
    const float scale = rsqrtf((float)CN);

    for (int i = tid; i < 64 * 64; i += 256) {
        int r = i >> 6, d = i & 63;
        qs[r][d] = qkv[((size_t)(b * TN + t0 + r)) * QKVN + h * DN + d];
    }

    float m[4], l[4], acc[4][4];
    #pragma unroll
    for (int i = 0; i < 4; i++) {
        m[i] = -1e30f; l[i] = 0.f;
        #pragma unroll
        for (int j = 0; j < 4; j++) acc[i][j] = 0.f;
    }

    int nS = (t0 + 64) / 32;
    for (int st = 0; st < nS; st++) {
        int s0 = st * 32;
        __syncthreads();
        for (int i = tid; i < 32 * 64; i += 256) {
            int r = i >> 6, d = i & 63;
            size_t base = ((size_t)(b * TN + s0 + r)) * QKVN + h * DN + d;
            ks[r][d] = qkv[base + CN];
            vs[r][d] = qkv[base + 2 * CN];
        }
        __syncthreads();

        float s[4][2];
        #pragma unroll
        for (int i = 0; i < 4; i++) { s[i][0] = 0.f; s[i][1] = 0.f; }
        #pragma unroll 8
        for (int d = 0; d < 64; d++) {
            float k0 = ks[c * 2][d], k1 = ks[c * 2 + 1][d];
            #pragma unroll
            for (int i = 0; i < 4; i++) {
                float qv = qs[trow + i][d];
                s[i][0] = fmaf(qv, k0, s[i][0]);
                s[i][1] = fmaf(qv, k1, s[i][1]);
            }
        }
        #pragma unroll
        for (int i = 0; i < 4; i++) {
            int srow = t0 + trow + i;
            #pragma unroll
            for (int j = 0; j < 2; j++) {
                int scol = s0 + c * 2 + j;
                s[i][j] = (scol <= srow) ? s[i][j] * scale : -1e30f;
            }
        }

        float fac[4];
        #pragma unroll
        for (int i = 0; i < 4; i++) {
            float tm = fmaxf(s[i][0], s[i][1]);
            #pragma unroll
            for (int o = 1; o < 16; o <<= 1)
                tm = fmaxf(tm, __shfl_xor_sync(0xffffffffu, tm, o));
            float mn = fmaxf(m[i], tm);
            fac[i] = __expf(m[i] - mn);
            m[i] = mn;
            float p0 = __expf(s[i][0] - mn);
            float p1 = __expf(s[i][1] - mn);
            ps[trow + i][c * 2 + 0] = p0;
            ps[trow + i][c * 2 + 1] = p1;
            float rs = p0 + p1;
            #pragma unroll
            for (int o = 1; o < 16; o <<= 1)
                rs += __shfl_xor_sync(0xffffffffu, rs, o);
            l[i] = l[i] * fac[i] + rs;
        }
        #pragma unroll
        for (int i = 0; i < 4; i++)
            #pragma unroll
            for (int j = 0; j < 4; j++) acc[i][j] *= fac[i];
        __syncthreads();

        #pragma unroll 8
        for (int ss = 0; ss < 32; ss++) {
            float pv0 = ps[trow + 0][ss], pv1 = ps[trow + 1][ss];
            float pv2 = ps[trow + 2][ss], pv3 = ps[trow + 3][ss];
            #pragma unroll
            for (int j = 0; j < 4; j++) {
                float vv = vs[ss][c * 4 + j];
                acc[0][j] = fmaf(pv0, vv, acc[0][j]);
                acc[1][j] = fmaf(pv1, vv, acc[1][j]);
                acc[2][j] = fmaf(pv2, vv, acc[2][j]);
                acc[3][j] = fmaf(pv3, vv, acc[3][j]);
            }
        }
    }

    #pragma unroll
    for (int i = 0; i < 4; i++) {
        float inv = 1.f / l[i];
        float4 o4 = make_float4(f2tf_f(acc[i][0] * inv), f2tf_f(acc[i][1] * inv),
                                f2tf_f(acc[i][2] * inv), f2tf_f(acc[i][3] * inv));
        *(float4*)(att + ((size_t)(b * TN + t0 + trow + i)) * CN + h * DN + c * 4) = o4;
    }
}

// ---------------- host orchestration ----------------------------------------
extern "C" void kernel_launch(void* const* d_in, const int* in_sizes, int n_in,
                              void* d_out, int out_size) {
    const int*   x       = (const int*)  d_in[0];
    const float* tok_emb = (const float*)d_in[1];
    const float* pos_emb = (const float*)d_in[2];
    const float* Wq      = (const float*)d_in[3];
    const float* Wk      = (const float*)d_in[4];
    const float* Wv      = (const float*)d_in[5];
    const float* Wo      = (const float*)d_in[6];
    const float* bo      = (const float*)d_in[7];
    const float* ln1_g   = (const float*)d_in[8];
    const float* ln1_b   = (const float*)d_in[9];
    const float* ln2_g   = (const float*)d_in[10];
    const float* ln2_b   = (const float*)d_in[11];
    const float* W1      = (const float*)d_in[12];
    const float* b1      = (const float*)d_in[13];
    const float* W2      = (const float*)d_in[14];
    const float* b2      = (const float*)d_in[15];
    const float* lnf_g   = (const float*)d_in[16];
    const float* lnf_b   = (const float*)d_in[17];
    const float* Wh      = (const float*)d_in[18];
    const float* bh      = (const float*)d_in[19];
    float* out = (float*)d_out;

    float *ph, *pain, *pqkv, *patt, *pffn, *pwt, *pwoc, *pw1c, *pw2c, *pwhc;
    cudaGetSymbolAddress((void**)&ph,   g_h);
    cudaGetSymbolAddress((void**)&pain, g_ain);
    cudaGetSymbolAddress((void**)&pqkv, g_qkv);
    cudaGetSymbolAddress((void**)&patt, g_att);
    cudaGetSymbolAddress((void**)&pffn, g_ffn);
    cudaGetSymbolAddress((void**)&pwt,  g_wt);
    cudaGetSymbolAddress((void**)&pwoc, g_woc);
    cudaGetSymbolAddress((void**)&pw1c, g_w1c);
    cudaGetSymbolAddress((void**)&pw2c, g_w2c);
    cudaGetSymbolAddress((void**)&pwhc, g_whc);

    cudaFuncSetAttribute(tgemm_kernel,
                         cudaFuncAttributeMaxDynamicSharedMemorySize, TG_SMEM);

    const int HCD = HN * CN * DN;

    // one-time per-call tf32 weight conversions
    {
        int n4;
        n4 = CN * VN / 4;
        cvtf_kernel<<<(n4 + 255) / 256, 256>>>((const float4*)Wh, (float4*)pwhc, n4);
        n4 = LN * CN * CN / 4;
        cvtf_kernel<<<(n4 + 255) / 256, 256>>>((const float4*)Wo, (float4*)pwoc, n4);
        n4 = LN * CN * FN / 4;
        cvtf_kernel<<<(n4 + 255) / 256, 256>>>((const float4*)W1, (float4*)pw1c, n4);
        n4 = LN * FN * CN / 4;
        cvtf_kernel<<<(n4 + 255) / 256, 256>>>((const float4*)W2, (float4*)pw2c, n4);
    }

    embed_kernel<<<(BT * CN + 255) / 256, 256>>>(x, tok_emb, pos_emb, ph);

    for (int l = 0; l < LN; l++) {
        layernorm_kernel<<<BT, 256>>>(ph, ln1_g + l * CN, ln1_b + l * CN, pain);
        transpose_qkv_kernel<<<(3 * HCD + 255) / 256, 256>>>(
            Wq + (size_t)l * HCD, Wk + (size_t)l * HCD, Wv + (size_t)l * HCD, pwt);
        tgemm_kernel<<<dim3(QKVN / 128, BT / 128), 256, TG_SMEM>>>(
            pain, pwt, pqkv, nullptr, nullptr, BT, QKVN, CN, 0);
        flash_kernel<<<dim3(TN / 64, 1, BN_ * HN), 256>>>(pqkv, patt);
        tgemm_kernel<<<dim3(CN / 128, BT / 128), 256, TG_SMEM>>>(
            patt, pwoc + (size_t)l * CN * CN, ph, bo + l * CN, ph, BT, CN, CN, 0);
        layernorm_kernel<<<BT, 256>>>(ph, ln2_g + l * CN, ln2_b + l * CN, pain);
        tgemm_kernel<<<dim3(FN / 128, BT / 128), 256, TG_SMEM>>>(
            pain, pw1c + (size_t)l * CN * FN, pffn, b1 + l * FN, nullptr, BT, FN, CN, 1);
        tgemm_kernel<<<dim3(CN / 128, BT / 128), 256, TG_SMEM>>>(
            pffn, pw2c + (size_t)l * FN * CN, ph, b2 + l * CN, ph, BT, CN, FN, 0);
    }

    layernorm_kernel<<<BT, 256>>>(ph, lnf_g, lnf_b, pain);
    tgemm_kernel<<<dim3(VN / 128, BT / 128), 256, TG_SMEM>>>(
        pain, pwhc, out, bh, nullptr, BT, VN, CN, 0);
}